// round 13
// baseline (speedup 1.0000x reference)
#include <cuda_runtime.h>
#include <cuda_fp16.h>
#include <math.h>
#include <stdint.h>

#define D_MODEL 1024
#define N_EXP   8
#define N_TOK   4096
#define FFN_H   2048
#define CAP     N_TOK

// ---------------- device scratch ----------------
__device__ int   g_cnt[N_EXP];
__device__ int   g_tok[N_EXP * CAP];
__device__ int   g_slot[N_EXP * CAP];
__device__ float g_wt[N_EXP * CAP];
__device__ float g_psum[N_EXP];

__device__ __align__(16) __half g_x_f16[(size_t)N_TOK * D_MODEL];
__device__ __align__(16) __half g_w1_f16[(size_t)N_EXP * FFN_H * D_MODEL];
__device__ __align__(16) __half g_w2_f16[(size_t)N_EXP * D_MODEL * FFN_H];
__device__ __align__(16) __half g_h_f16[(size_t)2 * N_TOK * FFN_H];
__device__ __align__(16) float  g_y[(size_t)2 * N_TOK * D_MODEL];
__device__ __align__(16) float  g_y2[(size_t)2 * N_TOK * D_MODEL];

// ---------------- portable PTX helpers ----------------
__device__ __forceinline__ uint32_t smem_u32(const void* p) {
    uint32_t a;
    asm("{ .reg .u64 t; cvta.to.shared.u64 t, %1; cvt.u32.u64 %0, t; }" : "=r"(a) : "l"(p));
    return a;
}

#define CP16(dst, src) \
    asm volatile("cp.async.cg.shared.global [%0], [%1], 16;" :: "r"(dst), "l"(src))
#define CP_COMMIT() asm volatile("cp.async.commit_group;" ::: "memory")
#define CP_WAIT0()  asm volatile("cp.async.wait_group 0;" ::: "memory")

#define LDSM4(r, addr) \
    asm volatile("ldmatrix.sync.aligned.m8n8.x4.shared.b16 {%0,%1,%2,%3}, [%4];" \
                 : "=r"((r)[0]), "=r"((r)[1]), "=r"((r)[2]), "=r"((r)[3]) : "r"(addr))

#define MMA16816(c, a, b0, b1) \
    asm volatile("mma.sync.aligned.m16n8k16.row.col.f32.f16.f16.f32 " \
                 "{%0,%1,%2,%3}, {%4,%5,%6,%7}, {%8,%9}, {%0,%1,%2,%3};" \
                 : "+f"((c)[0]), "+f"((c)[1]), "+f"((c)[2]), "+f"((c)[3]) \
                 : "r"((a)[0]), "r"((a)[1]), "r"((a)[2]), "r"((a)[3]), \
                   "r"(b0), "r"(b1))

__device__ __forceinline__ uint32_t swz(uint32_t off) { return off ^ ((off >> 3) & 0x70); }

// ---------------- tile geometry (R7-proven) ----------------
#define BM 128
#define BN 128
#define BKT 64
#define OFF_A 0
#define OFF_B 16384
#define STAGE_TOTAL 32768
#define SMEM_DYN (2 * STAGE_TOTAL)

// ---------------- init counters ----------------
__global__ void init_kernel() {
    if (threadIdx.x < N_EXP) {
        g_cnt[threadIdx.x] = 0;
        g_psum[threadIdx.x] = 0.f;
    }
}

// ---------------- fp32 -> fp16 weight convert ----------------
__global__ __launch_bounds__(256) void cvt_w_kernel(const float4* __restrict__ w,
                                                    uint4* __restrict__ dst, int nw8) {
    int i = blockIdx.x * blockDim.x + threadIdx.x;
    if (i >= nw8) return;
    const float4* src = w + 2 * (size_t)i;
    float4 a = src[0], b = src[1];
    __half2 h0 = __floats2half2_rn(a.x, a.y), h1 = __floats2half2_rn(a.z, a.w);
    __half2 h2 = __floats2half2_rn(b.x, b.y), h3 = __floats2half2_rn(b.z, b.w);
    uint4 o;
    o.x = *(uint32_t*)&h0; o.y = *(uint32_t*)&h1;
    o.z = *(uint32_t*)&h2; o.w = *(uint32_t*)&h3;
    dst[i] = o;
}

// ---------------- router: 4 warps/token, 2 tokens/block + fused x cvt + psum ------
__global__ __launch_bounds__(256) void router_kernel(const float4* __restrict__ x4,
                                                     const float4* __restrict__ rw4) {
    const int lane = threadIdx.x & 31;
    const int wid = threadIdx.x >> 5;          // 0..7
    const int tkn = wid >> 2;                  // 0..1 token within block
    const int q = wid & 3;                     // 0..3 quarter of D
    const int n = blockIdx.x * 2 + tkn;

    __shared__ float pl[8][N_EXP];             // per-warp partial logits
    __shared__ float sp2[2][N_EXP];            // per-token probs (for psum)

    const float4* xr = x4 + (size_t)n * (D_MODEL / 4) + q * 64;
    uint2* xo = (uint2*)(g_x_f16 + (size_t)n * D_MODEL) + q * 64;
    const float4* rwq = rw4 + q * 64;

    float part[N_EXP];
#pragma unroll
    for (int e = 0; e < N_EXP; e++) part[e] = 0.f;
#pragma unroll
    for (int i = 0; i < 2; i++) {
        float4 v = xr[lane + 32 * i];
        __half2 p0 = __floats2half2_rn(v.x, v.y);
        __half2 p1 = __floats2half2_rn(v.z, v.w);
        uint2 pk;
        pk.x = *(uint32_t*)&p0; pk.y = *(uint32_t*)&p1;
        xo[lane + 32 * i] = pk;
#pragma unroll
        for (int e = 0; e < N_EXP; e++) {
            float4 w = rwq[e * (D_MODEL / 4) + lane + 32 * i];
            part[e] += v.x * w.x + v.y * w.y + v.z * w.z + v.w * w.w;
        }
    }
#pragma unroll
    for (int o = 16; o > 0; o >>= 1) {
#pragma unroll
        for (int e = 0; e < N_EXP; e++)
            part[e] += __shfl_xor_sync(0xFFFFFFFF, part[e], o);
    }
    if (lane == 0) {
#pragma unroll
        for (int e = 0; e < N_EXP; e++) pl[wid][e] = part[e];
    }
    __syncthreads();

    // one thread per token finalizes
    if (threadIdx.x < 2) {
        const int t = threadIdx.x;
        const int nt = blockIdx.x * 2 + t;
        float logit[N_EXP];
#pragma unroll
        for (int e = 0; e < N_EXP; e++)
            logit[e] = (pl[4 * t][e] + pl[4 * t + 1][e]) + (pl[4 * t + 2][e] + pl[4 * t + 3][e]);
        float m = logit[0];
#pragma unroll
        for (int e = 1; e < N_EXP; e++) m = fmaxf(m, logit[e]);
        float p[N_EXP], s = 0.f;
#pragma unroll
        for (int e = 0; e < N_EXP; e++) { p[e] = expf(logit[e] - m); s += p[e]; }
        float inv = 1.f / s;
#pragma unroll
        for (int e = 0; e < N_EXP; e++) { p[e] *= inv; sp2[t][e] = p[e]; }
        int i1 = 0;
#pragma unroll
        for (int e = 1; e < N_EXP; e++) if (logit[e] > logit[i1]) i1 = e;
        int i2 = (i1 == 0) ? 1 : 0;
#pragma unroll
        for (int e = 0; e < N_EXP; e++) if (e != i1 && logit[e] > logit[i2]) i2 = e;
        float denom = p[i1] + p[i2];
        int pos1 = atomicAdd(&g_cnt[i1], 1);
        g_tok[i1 * CAP + pos1] = nt; g_slot[i1 * CAP + pos1] = 2 * nt; g_wt[i1 * CAP + pos1] = p[i1] / denom;
        int pos2 = atomicAdd(&g_cnt[i2], 1);
        g_tok[i2 * CAP + pos2] = nt; g_slot[i2 * CAP + pos2] = 2 * nt + 1; g_wt[i2 * CAP + pos2] = p[i2] / denom;
    }
    __syncthreads();
    if (threadIdx.x < N_EXP) {
        float s = sp2[0][threadIdx.x] + sp2[1][threadIdx.x];
        atomicAdd(&g_psum[threadIdx.x], s);
    }
}

// ---------------- stage loader / compute (R7-proven) ----------------
__device__ __forceinline__ void load_stage(uint32_t st, int lr, int lc0,
                                           const __half* a, const __half* b, int k0) {
#pragma unroll
    for (int j = 0; j < 4; j++) {
        uint32_t off = (uint32_t)lr * 128 + (lc0 + j) * 16;
        uint32_t so = swz(off);
        CP16(st + OFF_A + so, (const void*)(a + k0 + (lc0 + j) * 8));
        CP16(st + OFF_B + so, (const void*)(b + k0 + (lc0 + j) * 8));
    }
    CP_COMMIT();
}

__device__ __forceinline__ void compute_stage(uint32_t sb, float acc[4][4][4],
                                              int wm, int wn, int lane) {
    const int arow = lane & 15, ahalf = lane >> 4;
    const int nrow = ((lane >> 4) & 1) * 8 + (lane & 7);
    const int bhalf = (lane >> 3) & 1;
#pragma unroll
    for (int kk = 0; kk < 4; kk++) {
        uint32_t ah[4][4], bf[2][4];
#pragma unroll
        for (int mi = 0; mi < 4; mi++) {
            uint32_t off = (uint32_t)(wm * 64 + mi * 16 + arow) * 128 + kk * 32 + ahalf * 16;
            LDSM4(ah[mi], sb + OFF_A + swz(off));
        }
#pragma unroll
        for (int p = 0; p < 2; p++) {
            uint32_t off = (uint32_t)(wn * 32 + p * 16 + nrow) * 128 + kk * 32 + bhalf * 16;
            LDSM4(bf[p], sb + OFF_B + swz(off));
        }
#pragma unroll
        for (int mi = 0; mi < 4; mi++) {
#pragma unroll
            for (int p = 0; p < 2; p++) {
                MMA16816(acc[mi][2 * p],     ah[mi], bf[p][0], bf[p][1]);
                MMA16816(acc[mi][2 * p + 1], ah[mi], bf[p][2], bf[p][3]);
            }
        }
    }
}

// ============ grouped GEMM1: h[slot] = silu(x[tok] @ w1[e]^T + b1[e]) ============
__global__ __launch_bounds__(256, 2) void gemm1_mma(const float* __restrict__ b1) {
    const int e = blockIdx.z;
    const int cnt = g_cnt[e];
    const int row0 = blockIdx.y * BM;
    if (row0 >= cnt) return;
    const int col0 = blockIdx.x * BN;

    extern __shared__ char sm[];
    __shared__ int toks[BM];
    __shared__ int slots[BM];

    const int tid = threadIdx.x;
    if (tid < BM) {
        int r = row0 + tid;
        toks[tid]  = (r < cnt) ? g_tok[e * CAP + r]  : 0;
        slots[tid] = (r < cnt) ? g_slot[e * CAP + r] : -1;
    }
    __syncthreads();

    const uint32_t smb = smem_u32(sm);
    const int lr = tid >> 1;
    const int lc0 = (tid & 1) * 4;

    const __half* aP = g_x_f16 + (size_t)toks[lr] * D_MODEL;
    const __half* bP = g_w1_f16 + ((size_t)e * FFN_H + col0 + lr) * D_MODEL;

    float acc[4][4][4];
#pragma unroll
    for (int mi = 0; mi < 4; mi++)
#pragma unroll
        for (int ni = 0; ni < 4; ni++)
#pragma unroll
            for (int q = 0; q < 4; q++) acc[mi][ni][q] = 0.f;

    const int lane = tid & 31;
    const int wid = tid >> 5;
    const int wm = wid >> 2, wn = wid & 3;
    const int NT = D_MODEL / BKT;   // 16

    load_stage(smb, lr, lc0, aP, bP, 0);

#pragma unroll 1
    for (int it = 0; it < NT; it++) {
        CP_WAIT0();
        __syncthreads();
        if (it + 1 < NT)
            load_stage(smb + ((it + 1) & 1) * STAGE_TOTAL, lr, lc0, aP, bP, (it + 1) * BKT);
        compute_stage(smb + (it & 1) * STAGE_TOTAL, acc, wm, wn, lane);
        __syncthreads();
    }

    // epilogue: bias + silu + fp16 store
    const int gr = lane >> 2, gc2 = (lane & 3) * 2;
    const float* b1e = b1 + (size_t)e * FFN_H;
#pragma unroll
    for (int mi = 0; mi < 4; mi++) {
#pragma unroll
        for (int ni = 0; ni < 4; ni++) {
            int col = col0 + wn * 32 + ni * 8 + gc2;
            float bv0 = b1e[col], bv1 = b1e[col + 1];
#pragma unroll
            for (int half = 0; half < 2; half++) {
                int r = wm * 64 + mi * 16 + gr + half * 8;
                int slot = slots[r];
                if (slot >= 0) {
                    float v0 = acc[mi][ni][half * 2 + 0] + bv0;
                    float v1 = acc[mi][ni][half * 2 + 1] + bv1;
                    float s0 = v0 / (1.f + expf(-v0));
                    float s1 = v1 / (1.f + expf(-v1));
                    *(__half2*)(g_h_f16 + (size_t)slot * FFN_H + col) = __floats2half2_rn(s0, s1);
                }
            }
        }
    }
}

// ============ grouped GEMM2 (split-K=2): partial y over K half ============
__global__ __launch_bounds__(256, 2) void gemm2_mma(const float* __restrict__ b2) {
    const int e = blockIdx.z;
    const int cnt = g_cnt[e];
    const int row0 = blockIdx.y * BM;
    if (row0 >= cnt) return;
    const int kh = blockIdx.x & 1;                 // K half
    const int col0 = (blockIdx.x >> 1) * BN;
    const int kbase = kh * (FFN_H / 2);

    extern __shared__ char sm[];
    __shared__ float wts[BM];
    __shared__ int   slots[BM];

    const int tid = threadIdx.x;
    if (tid < BM) {
        int r = row0 + tid;
        slots[tid] = (r < cnt) ? g_slot[e * CAP + r] : -1;
        wts[tid]   = (r < cnt) ? g_wt[e * CAP + r]   : 0.f;
    }
    __syncthreads();

    const uint32_t smb = smem_u32(sm);
    const int lr = tid >> 1;
    const int lc0 = (tid & 1) * 4;

    const int aslot = (slots[lr] < 0) ? 0 : slots[lr];
    const __half* aP = g_h_f16 + (size_t)aslot * FFN_H + kbase;
    const __half* bP = g_w2_f16 + ((size_t)e * D_MODEL + col0 + lr) * FFN_H + kbase;

    float acc[4][4][4];
#pragma unroll
    for (int mi = 0; mi < 4; mi++)
#pragma unroll
        for (int ni = 0; ni < 4; ni++)
#pragma unroll
            for (int q = 0; q < 4; q++) acc[mi][ni][q] = 0.f;

    const int lane = tid & 31;
    const int wid = tid >> 5;
    const int wm = wid >> 2, wn = wid & 3;
    const int NT = (FFN_H / 2) / BKT;   // 16

    load_stage(smb, lr, lc0, aP, bP, 0);

#pragma unroll 1
    for (int it = 0; it < NT; it++) {
        CP_WAIT0();
        __syncthreads();
        if (it + 1 < NT)
            load_stage(smb + ((it + 1) & 1) * STAGE_TOTAL, lr, lc0, aP, bP, (it + 1) * BKT);
        compute_stage(smb + (it & 1) * STAGE_TOTAL, acc, wm, wn, lane);
        __syncthreads();
    }

    // epilogue: weighted (+bias in half 0) store to per-slot, per-half scratch
    const int gr = lane >> 2, gc2 = (lane & 3) * 2;
    const float* b2e = b2 + (size_t)e * D_MODEL;
    float* yout = (kh == 0) ? g_y : g_y2;
#pragma unroll
    for (int mi = 0; mi < 4; mi++) {
#pragma unroll
        for (int ni = 0; ni < 4; ni++) {
            int col = col0 + wn * 32 + ni * 8 + gc2;
            float bv0 = (kh == 0) ? b2e[col]     : 0.f;
            float bv1 = (kh == 0) ? b2e[col + 1] : 0.f;
#pragma unroll
            for (int half = 0; half < 2; half++) {
                int r = wm * 64 + mi * 16 + gr + half * 8;
                int slot = slots[r];
                if (slot >= 0) {
                    float wt = wts[r];
                    float2 v;
                    v.x = (acc[mi][ni][half * 2 + 0] + bv0) * wt;
                    v.y = (acc[mi][ni][half * 2 + 1] + bv1) * wt;
                    *(float2*)(yout + (size_t)slot * D_MODEL + col) = v;
                }
            }
        }
    }
}

// ---------------- combine: out[n] = sum of 4 partials; + aux loss ----------------
__global__ __launch_bounds__(256) void combine_kernel(float4* __restrict__ out4,
                                                      float* __restrict__ out,
                                                      int out_size) {
    int i = blockIdx.x * blockDim.x + threadIdx.x;
    const int D4 = D_MODEL / 4;
    if (i < N_TOK * D4) {
        int n = i / D4, rem = i - n * D4;
        size_t ia = (size_t)(2 * n) * D4 + rem;
        size_t ib = (size_t)(2 * n + 1) * D4 + rem;
        float4 a0 = ((const float4*)g_y)[ia],  a1 = ((const float4*)g_y2)[ia];
        float4 b0 = ((const float4*)g_y)[ib],  b1 = ((const float4*)g_y2)[ib];
        float4 r;
        r.x = (a0.x + a1.x) + (b0.x + b1.x);
        r.y = (a0.y + a1.y) + (b0.y + b1.y);
        r.z = (a0.z + a1.z) + (b0.z + b1.z);
        r.w = (a0.w + a1.w) + (b0.w + b1.w);
        out4[i] = r;
    }
    if (blockIdx.x == 0 && threadIdx.x == 0 && out_size > N_TOK * D_MODEL) {
        float a = 0.f;
#pragma unroll
        for (int e = 0; e < N_EXP; e++) {
            float f = (float)g_cnt[e] / (float)(N_TOK * 2);
            float P = g_psum[e] / (float)N_TOK;
            a += f * P;
        }
        out[N_TOK * D_MODEL] = a * (float)N_EXP;
    }
}

// ---------------- launch ----------------
extern "C" void kernel_launch(void* const* d_in, const int* in_sizes, int n_in,
                              void* d_out, int out_size) {
    const float* x  = (const float*)d_in[0];
    const float* rw = (const float*)d_in[1];
    const float* w1 = (const float*)d_in[2];
    const float* b1 = (const float*)d_in[3];
    const float* w2 = (const float*)d_in[4];
    const float* b2 = (const float*)d_in[5];
    float* out = (float*)d_out;

    // one-time resource setup (first call = correctness run, pre-capture)
    static cudaStream_t s2 = nullptr;
    static cudaEvent_t evFork = nullptr, ev1 = nullptr, ev2 = nullptr;
    if (s2 == nullptr) {
        cudaStreamCreateWithFlags(&s2, cudaStreamNonBlocking);
        cudaEventCreateWithFlags(&evFork, cudaEventDisableTiming);
        cudaEventCreateWithFlags(&ev1, cudaEventDisableTiming);
        cudaEventCreateWithFlags(&ev2, cudaEventDisableTiming);
        cudaFuncSetAttribute(gemm1_mma, cudaFuncAttributeMaxDynamicSharedMemorySize, SMEM_DYN);
        cudaFuncSetAttribute(gemm2_mma, cudaFuncAttributeMaxDynamicSharedMemorySize, SMEM_DYN);
    }

    __half *w1h, *w2h;
    cudaGetSymbolAddress((void**)&w1h, g_w1_f16);
    cudaGetSymbolAddress((void**)&w2h, g_w2_f16);

    // fork: side stream does the weight conversions
    cudaEventRecord(evFork, 0);
    cudaStreamWaitEvent(s2, evFork, 0);
    const int nw8 = N_EXP * FFN_H * D_MODEL / 8;
    cvt_w_kernel<<<(nw8 + 255) / 256, 256, 0, s2>>>((const float4*)w1, (uint4*)w1h, nw8);
    cudaEventRecord(ev1, s2);
    cvt_w_kernel<<<(nw8 + 255) / 256, 256, 0, s2>>>((const float4*)w2, (uint4*)w2h, nw8);
    cudaEventRecord(ev2, s2);

    // main stream: routing pipeline
    init_kernel<<<1, 32>>>();
    router_kernel<<<N_TOK / 2, 256>>>((const float4*)x, (const float4*)rw);

    cudaStreamWaitEvent(0, ev1, 0);            // w1 ready
    dim3 g1(FFN_H / BN, N_TOK / BM, N_EXP);
    gemm1_mma<<<g1, 256, SMEM_DYN>>>(b1);

    cudaStreamWaitEvent(0, ev2, 0);            // w2 ready
    dim3 g2(2 * D_MODEL / BN, N_TOK / BM, N_EXP);   // x dim: col * 2 K-halves
    gemm2_mma<<<g2, 256, SMEM_DYN>>>(b2);

    const int nc = N_TOK * (D_MODEL / 4);
    combine_kernel<<<(nc + 255) / 256, 256>>>((float4*)out, out, out_size);
}

// round 14
// speedup vs baseline: 1.0146x; 1.0146x over previous
#include <cuda_runtime.h>
#include <cuda_fp16.h>
#include <math.h>
#include <stdint.h>

#define D_MODEL 1024
#define N_EXP   8
#define N_TOK   4096
#define FFN_H   2048
#define CAP     N_TOK

// ---------------- device scratch ----------------
__device__ int   g_cnt[N_EXP];
__device__ int   g_tok[N_EXP * CAP];
__device__ int   g_slot[N_EXP * CAP];
__device__ float g_wt[N_EXP * CAP];
__device__ float g_psum[N_EXP];

__device__ __align__(16) __half g_x_f16[(size_t)N_TOK * D_MODEL];
__device__ __align__(16) __half g_w1_f16[(size_t)N_EXP * FFN_H * D_MODEL];
__device__ __align__(16) __half g_w2_f16[(size_t)N_EXP * D_MODEL * FFN_H];
__device__ __align__(16) __half g_h_f16[(size_t)2 * N_TOK * FFN_H];
__device__ __align__(16) float  g_y[(size_t)2 * N_TOK * D_MODEL];

// ---------------- portable PTX helpers ----------------
__device__ __forceinline__ uint32_t smem_u32(const void* p) {
    uint32_t a;
    asm("{ .reg .u64 t; cvta.to.shared.u64 t, %1; cvt.u32.u64 %0, t; }" : "=r"(a) : "l"(p));
    return a;
}

#define CP16(dst, src) \
    asm volatile("cp.async.cg.shared.global [%0], [%1], 16;" :: "r"(dst), "l"(src))
#define CP_COMMIT() asm volatile("cp.async.commit_group;" ::: "memory")
#define CP_WAIT0()  asm volatile("cp.async.wait_group 0;" ::: "memory")

#define LDSM4(r, addr) \
    asm volatile("ldmatrix.sync.aligned.m8n8.x4.shared.b16 {%0,%1,%2,%3}, [%4];" \
                 : "=r"((r)[0]), "=r"((r)[1]), "=r"((r)[2]), "=r"((r)[3]) : "r"(addr))

#define MMA16816(c, a, b0, b1) \
    asm volatile("mma.sync.aligned.m16n8k16.row.col.f32.f16.f16.f32 " \
                 "{%0,%1,%2,%3}, {%4,%5,%6,%7}, {%8,%9}, {%0,%1,%2,%3};" \
                 : "+f"((c)[0]), "+f"((c)[1]), "+f"((c)[2]), "+f"((c)[3]) \
                 : "r"((a)[0]), "r"((a)[1]), "r"((a)[2]), "r"((a)[3]), \
                   "r"(b0), "r"(b1))

__device__ __forceinline__ uint32_t swz(uint32_t off) { return off ^ ((off >> 3) & 0x70); }

// ---------------- tile geometry (R7-proven) ----------------
#define BM 128
#define BN 128
#define BKT 64
#define OFF_A 0
#define OFF_B 16384
#define STAGE_TOTAL 32768
#define SMEM_DYN (2 * STAGE_TOTAL)

// ---------------- init counters ----------------
__global__ void init_kernel() {
    if (threadIdx.x < N_EXP) {
        g_cnt[threadIdx.x] = 0;
        g_psum[threadIdx.x] = 0.f;
    }
}

// ---------------- fp32 -> fp16 weight convert ----------------
__global__ __launch_bounds__(256) void cvt_w_kernel(const float4* __restrict__ w,
                                                    uint4* __restrict__ dst, int nw8) {
    int i = blockIdx.x * blockDim.x + threadIdx.x;
    if (i >= nw8) return;
    const float4* src = w + 2 * (size_t)i;
    float4 a = src[0], b = src[1];
    __half2 h0 = __floats2half2_rn(a.x, a.y), h1 = __floats2half2_rn(a.z, a.w);
    __half2 h2 = __floats2half2_rn(b.x, b.y), h3 = __floats2half2_rn(b.z, b.w);
    uint4 o;
    o.x = *(uint32_t*)&h0; o.y = *(uint32_t*)&h1;
    o.z = *(uint32_t*)&h2; o.w = *(uint32_t*)&h3;
    dst[i] = o;
}

// ---------------- router: 4 warps/token, 2 tokens/block + fused x cvt + psum ------
__global__ __launch_bounds__(256) void router_kernel(const float4* __restrict__ x4,
                                                     const float4* __restrict__ rw4) {
    const int lane = threadIdx.x & 31;
    const int wid = threadIdx.x >> 5;          // 0..7
    const int tkn = wid >> 2;                  // 0..1 token within block
    const int q = wid & 3;                     // 0..3 quarter of D
    const int n = blockIdx.x * 2 + tkn;

    __shared__ float pl[8][N_EXP];             // per-warp partial logits
    __shared__ float sp2[2][N_EXP];            // per-token probs (for psum)

    const float4* xr = x4 + (size_t)n * (D_MODEL / 4) + q * 64;
    uint2* xo = (uint2*)(g_x_f16 + (size_t)n * D_MODEL) + q * 64;
    const float4* rwq = rw4 + q * 64;

    float part[N_EXP];
#pragma unroll
    for (int e = 0; e < N_EXP; e++) part[e] = 0.f;
#pragma unroll
    for (int i = 0; i < 2; i++) {
        float4 v = xr[lane + 32 * i];
        __half2 p0 = __floats2half2_rn(v.x, v.y);
        __half2 p1 = __floats2half2_rn(v.z, v.w);
        uint2 pk;
        pk.x = *(uint32_t*)&p0; pk.y = *(uint32_t*)&p1;
        xo[lane + 32 * i] = pk;
#pragma unroll
        for (int e = 0; e < N_EXP; e++) {
            float4 w = rwq[e * (D_MODEL / 4) + lane + 32 * i];
            part[e] += v.x * w.x + v.y * w.y + v.z * w.z + v.w * w.w;
        }
    }
#pragma unroll
    for (int o = 16; o > 0; o >>= 1) {
#pragma unroll
        for (int e = 0; e < N_EXP; e++)
            part[e] += __shfl_xor_sync(0xFFFFFFFF, part[e], o);
    }
    if (lane == 0) {
#pragma unroll
        for (int e = 0; e < N_EXP; e++) pl[wid][e] = part[e];
    }
    __syncthreads();

    // one thread per token finalizes
    if (threadIdx.x < 2) {
        const int t = threadIdx.x;
        const int nt = blockIdx.x * 2 + t;
        float logit[N_EXP];
#pragma unroll
        for (int e = 0; e < N_EXP; e++)
            logit[e] = (pl[4 * t][e] + pl[4 * t + 1][e]) + (pl[4 * t + 2][e] + pl[4 * t + 3][e]);
        float m = logit[0];
#pragma unroll
        for (int e = 1; e < N_EXP; e++) m = fmaxf(m, logit[e]);
        float p[N_EXP], s = 0.f;
#pragma unroll
        for (int e = 0; e < N_EXP; e++) { p[e] = expf(logit[e] - m); s += p[e]; }
        float inv = 1.f / s;
#pragma unroll
        for (int e = 0; e < N_EXP; e++) { p[e] *= inv; sp2[t][e] = p[e]; }
        int i1 = 0;
#pragma unroll
        for (int e = 1; e < N_EXP; e++) if (logit[e] > logit[i1]) i1 = e;
        int i2 = (i1 == 0) ? 1 : 0;
#pragma unroll
        for (int e = 0; e < N_EXP; e++) if (e != i1 && logit[e] > logit[i2]) i2 = e;
        float denom = p[i1] + p[i2];
        int pos1 = atomicAdd(&g_cnt[i1], 1);
        g_tok[i1 * CAP + pos1] = nt; g_slot[i1 * CAP + pos1] = 2 * nt; g_wt[i1 * CAP + pos1] = p[i1] / denom;
        int pos2 = atomicAdd(&g_cnt[i2], 1);
        g_tok[i2 * CAP + pos2] = nt; g_slot[i2 * CAP + pos2] = 2 * nt + 1; g_wt[i2 * CAP + pos2] = p[i2] / denom;
    }
    __syncthreads();
    if (threadIdx.x < N_EXP) {
        float s = sp2[0][threadIdx.x] + sp2[1][threadIdx.x];
        atomicAdd(&g_psum[threadIdx.x], s);
    }
}

// ---------------- stage loader / compute (R7-proven) ----------------
__device__ __forceinline__ void load_stage(uint32_t st, int lr, int lc0,
                                           const __half* a, const __half* b, int k0) {
#pragma unroll
    for (int j = 0; j < 4; j++) {
        uint32_t off = (uint32_t)lr * 128 + (lc0 + j) * 16;
        uint32_t so = swz(off);
        CP16(st + OFF_A + so, (const void*)(a + k0 + (lc0 + j) * 8));
        CP16(st + OFF_B + so, (const void*)(b + k0 + (lc0 + j) * 8));
    }
    CP_COMMIT();
}

__device__ __forceinline__ void compute_stage(uint32_t sb, float acc[4][4][4],
                                              int wm, int wn, int lane) {
    const int arow = lane & 15, ahalf = lane >> 4;
    const int nrow = ((lane >> 4) & 1) * 8 + (lane & 7);
    const int bhalf = (lane >> 3) & 1;
#pragma unroll
    for (int kk = 0; kk < 4; kk++) {
        uint32_t ah[4][4], bf[2][4];
#pragma unroll
        for (int mi = 0; mi < 4; mi++) {
            uint32_t off = (uint32_t)(wm * 64 + mi * 16 + arow) * 128 + kk * 32 + ahalf * 16;
            LDSM4(ah[mi], sb + OFF_A + swz(off));
        }
#pragma unroll
        for (int p = 0; p < 2; p++) {
            uint32_t off = (uint32_t)(wn * 32 + p * 16 + nrow) * 128 + kk * 32 + bhalf * 16;
            LDSM4(bf[p], sb + OFF_B + swz(off));
        }
#pragma unroll
        for (int mi = 0; mi < 4; mi++) {
#pragma unroll
            for (int p = 0; p < 2; p++) {
                MMA16816(acc[mi][2 * p],     ah[mi], bf[p][0], bf[p][1]);
                MMA16816(acc[mi][2 * p + 1], ah[mi], bf[p][2], bf[p][3]);
            }
        }
    }
}

// ============ grouped GEMM1: h[slot] = silu(x[tok] @ w1[e]^T + b1[e]) ============
__global__ __launch_bounds__(256, 2) void gemm1_mma(const float* __restrict__ b1) {
    const int e = blockIdx.z;
    const int cnt = g_cnt[e];
    const int row0 = blockIdx.y * BM;
    if (row0 >= cnt) return;
    const int col0 = blockIdx.x * BN;

    extern __shared__ char sm[];
    __shared__ int toks[BM];
    __shared__ int slots[BM];

    const int tid = threadIdx.x;
    if (tid < BM) {
        int r = row0 + tid;
        toks[tid]  = (r < cnt) ? g_tok[e * CAP + r]  : 0;
        slots[tid] = (r < cnt) ? g_slot[e * CAP + r] : -1;
    }
    __syncthreads();

    const uint32_t smb = smem_u32(sm);
    const int lr = tid >> 1;
    const int lc0 = (tid & 1) * 4;

    const __half* aP = g_x_f16 + (size_t)toks[lr] * D_MODEL;
    const __half* bP = g_w1_f16 + ((size_t)e * FFN_H + col0 + lr) * D_MODEL;

    float acc[4][4][4];
#pragma unroll
    for (int mi = 0; mi < 4; mi++)
#pragma unroll
        for (int ni = 0; ni < 4; ni++)
#pragma unroll
            for (int q = 0; q < 4; q++) acc[mi][ni][q] = 0.f;

    const int lane = tid & 31;
    const int wid = tid >> 5;
    const int wm = wid >> 2, wn = wid & 3;
    const int NT = D_MODEL / BKT;   // 16

    load_stage(smb, lr, lc0, aP, bP, 0);

#pragma unroll 1
    for (int it = 0; it < NT; it++) {
        CP_WAIT0();
        __syncthreads();
        if (it + 1 < NT)
            load_stage(smb + ((it + 1) & 1) * STAGE_TOTAL, lr, lc0, aP, bP, (it + 1) * BKT);
        compute_stage(smb + (it & 1) * STAGE_TOTAL, acc, wm, wn, lane);
        __syncthreads();
    }

    // epilogue: bias + silu + fp16 store
    const int gr = lane >> 2, gc2 = (lane & 3) * 2;
    const float* b1e = b1 + (size_t)e * FFN_H;
#pragma unroll
    for (int mi = 0; mi < 4; mi++) {
#pragma unroll
        for (int ni = 0; ni < 4; ni++) {
            int col = col0 + wn * 32 + ni * 8 + gc2;
            float bv0 = b1e[col], bv1 = b1e[col + 1];
#pragma unroll
            for (int half = 0; half < 2; half++) {
                int r = wm * 64 + mi * 16 + gr + half * 8;
                int slot = slots[r];
                if (slot >= 0) {
                    float v0 = acc[mi][ni][half * 2 + 0] + bv0;
                    float v1 = acc[mi][ni][half * 2 + 1] + bv1;
                    float s0 = v0 / (1.f + expf(-v0));
                    float s1 = v1 / (1.f + expf(-v1));
                    *(__half2*)(g_h_f16 + (size_t)slot * FFN_H + col) = __floats2half2_rn(s0, s1);
                }
            }
        }
    }
}

// ============ grouped GEMM2: y[slot] = wt * (h[slot] @ w2[e]^T + b2[e]) ============
__global__ __launch_bounds__(256, 2) void gemm2_mma(const float* __restrict__ b2) {
    const int e = blockIdx.z;
    const int cnt = g_cnt[e];
    const int row0 = blockIdx.y * BM;
    if (row0 >= cnt) return;
    const int col0 = blockIdx.x * BN;

    extern __shared__ char sm[];
    __shared__ float wts[BM];
    __shared__ int   slots[BM];

    const int tid = threadIdx.x;
    if (tid < BM) {
        int r = row0 + tid;
        slots[tid] = (r < cnt) ? g_slot[e * CAP + r] : -1;
        wts[tid]   = (r < cnt) ? g_wt[e * CAP + r]   : 0.f;
    }
    __syncthreads();

    const uint32_t smb = smem_u32(sm);
    const int lr = tid >> 1;
    const int lc0 = (tid & 1) * 4;

    const int aslot = (slots[lr] < 0) ? 0 : slots[lr];
    const __half* aP = g_h_f16 + (size_t)aslot * FFN_H;
    const __half* bP = g_w2_f16 + ((size_t)e * D_MODEL + col0 + lr) * FFN_H;

    float acc[4][4][4];
#pragma unroll
    for (int mi = 0; mi < 4; mi++)
#pragma unroll
        for (int ni = 0; ni < 4; ni++)
#pragma unroll
            for (int q = 0; q < 4; q++) acc[mi][ni][q] = 0.f;

    const int lane = tid & 31;
    const int wid = tid >> 5;
    const int wm = wid >> 2, wn = wid & 3;
    const int NT = FFN_H / BKT;   // 32

    load_stage(smb, lr, lc0, aP, bP, 0);

#pragma unroll 1
    for (int it = 0; it < NT; it++) {
        CP_WAIT0();
        __syncthreads();
        if (it + 1 < NT)
            load_stage(smb + ((it + 1) & 1) * STAGE_TOTAL, lr, lc0, aP, bP, (it + 1) * BKT);
        compute_stage(smb + (it & 1) * STAGE_TOTAL, acc, wm, wn, lane);
        __syncthreads();
    }

    // epilogue: weighted + biased store to per-slot scratch (no atomics)
    const int gr = lane >> 2, gc2 = (lane & 3) * 2;
    const float* b2e = b2 + (size_t)e * D_MODEL;
#pragma unroll
    for (int mi = 0; mi < 4; mi++) {
#pragma unroll
        for (int ni = 0; ni < 4; ni++) {
            int col = col0 + wn * 32 + ni * 8 + gc2;
            float bv0 = b2e[col], bv1 = b2e[col + 1];
#pragma unroll
            for (int half = 0; half < 2; half++) {
                int r = wm * 64 + mi * 16 + gr + half * 8;
                int slot = slots[r];
                if (slot >= 0) {
                    float wt = wts[r];
                    float2 v;
                    v.x = (acc[mi][ni][half * 2 + 0] + bv0) * wt;
                    v.y = (acc[mi][ni][half * 2 + 1] + bv1) * wt;
                    *(float2*)(g_y + (size_t)slot * D_MODEL + col) = v;
                }
            }
        }
    }
}

// ---------------- combine: out[n] = y[2n] + y[2n+1]; + aux loss ----------------
__global__ __launch_bounds__(256) void combine_kernel(float4* __restrict__ out4,
                                                      float* __restrict__ out,
                                                      int out_size) {
    int i = blockIdx.x * blockDim.x + threadIdx.x;
    const int D4 = D_MODEL / 4;
    if (i < N_TOK * D4) {
        int n = i / D4, rem = i - n * D4;
        const float4* ya = (const float4*)g_y + (size_t)(2 * n) * D4 + rem;
        const float4* yb = (const float4*)g_y + (size_t)(2 * n + 1) * D4 + rem;
        float4 a = *ya, b = *yb;
        float4 r;
        r.x = a.x + b.x; r.y = a.y + b.y; r.z = a.z + b.z; r.w = a.w + b.w;
        out4[i] = r;
    }
    if (blockIdx.x == 0 && threadIdx.x == 0 && out_size > N_TOK * D_MODEL) {
        float a = 0.f;
#pragma unroll
        for (int e = 0; e < N_EXP; e++) {
            float f = (float)g_cnt[e] / (float)(N_TOK * 2);
            float P = g_psum[e] / (float)N_TOK;
            a += f * P;
        }
        out[N_TOK * D_MODEL] = a * (float)N_EXP;
    }
}

// ---------------- launch (R12 topology + R13 router) ----------------
extern "C" void kernel_launch(void* const* d_in, const int* in_sizes, int n_in,
                              void* d_out, int out_size) {
    const float* x  = (const float*)d_in[0];
    const float* rw = (const float*)d_in[1];
    const float* w1 = (const float*)d_in[2];
    const float* b1 = (const float*)d_in[3];
    const float* w2 = (const float*)d_in[4];
    const float* b2 = (const float*)d_in[5];
    float* out = (float*)d_out;

    // one-time resource setup (first call = correctness run, pre-capture)
    static cudaStream_t s2 = nullptr;
    static cudaEvent_t evFork = nullptr, ev1 = nullptr, ev2 = nullptr;
    if (s2 == nullptr) {
        cudaStreamCreateWithFlags(&s2, cudaStreamNonBlocking);
        cudaEventCreateWithFlags(&evFork, cudaEventDisableTiming);
        cudaEventCreateWithFlags(&ev1, cudaEventDisableTiming);
        cudaEventCreateWithFlags(&ev2, cudaEventDisableTiming);
        cudaFuncSetAttribute(gemm1_mma, cudaFuncAttributeMaxDynamicSharedMemorySize, SMEM_DYN);
        cudaFuncSetAttribute(gemm2_mma, cudaFuncAttributeMaxDynamicSharedMemorySize, SMEM_DYN);
    }

    __half *w1h, *w2h;
    cudaGetSymbolAddress((void**)&w1h, g_w1_f16);
    cudaGetSymbolAddress((void**)&w2h, g_w2_f16);

    // fork: side stream does the weight conversions
    cudaEventRecord(evFork, 0);
    cudaStreamWaitEvent(s2, evFork, 0);
    const int nw8 = N_EXP * FFN_H * D_MODEL / 8;
    cvt_w_kernel<<<(nw8 + 255) / 256, 256, 0, s2>>>((const float4*)w1, (uint4*)w1h, nw8);
    cudaEventRecord(ev1, s2);
    cvt_w_kernel<<<(nw8 + 255) / 256, 256, 0, s2>>>((const float4*)w2, (uint4*)w2h, nw8);
    cudaEventRecord(ev2, s2);

    // main stream: routing pipeline
    init_kernel<<<1, 32>>>();
    router_kernel<<<N_TOK / 2, 256>>>((const float4*)x, (const float4*)rw);

    cudaStreamWaitEvent(0, ev1, 0);            // w1 ready
    dim3 g1(FFN_H / BN, N_TOK / BM, N_EXP);
    gemm1_mma<<<g1, 256, SMEM_DYN>>>(b1);

    cudaStreamWaitEvent(0, ev2, 0);            // w2 ready
    dim3 g2(D_MODEL / BN, N_TOK / BM, N_EXP);
    gemm2_mma<<<g2, 256, SMEM_DYN>>>(b2);

    const int nc = N_TOK * (D_MODEL / 4);
    combine_kernel<<<(nc + 255) / 256, 256>>>((float4*)out, out, out_size);
}

// round 15
// speedup vs baseline: 1.0205x; 1.0059x over previous
#include <cuda_runtime.h>
#include <cuda_fp16.h>
#include <math.h>
#include <stdint.h>

#define D_MODEL 1024
#define N_EXP   8
#define N_TOK   4096
#define FFN_H   2048
#define CAP     N_TOK

// ---------------- device scratch (zero-initialized at module load) ----------------
__device__ int   g_cnt[N_EXP];
__device__ float g_psum[N_EXP];
__device__ int   g_tok[N_EXP * CAP];
__device__ int   g_slot[N_EXP * CAP];
__device__ float g_wt[N_EXP * CAP];

__device__ __align__(16) __half g_x_f16[(size_t)N_TOK * D_MODEL];
__device__ __align__(16) __half g_w1_f16[(size_t)N_EXP * FFN_H * D_MODEL];
__device__ __align__(16) __half g_w2_f16[(size_t)N_EXP * D_MODEL * FFN_H];
__device__ __align__(16) __half g_h_f16[(size_t)2 * N_TOK * FFN_H];
__device__ __align__(16) float  g_y[(size_t)2 * N_TOK * D_MODEL];

// ---------------- portable PTX helpers ----------------
__device__ __forceinline__ uint32_t smem_u32(const void* p) {
    uint32_t a;
    asm("{ .reg .u64 t; cvta.to.shared.u64 t, %1; cvt.u32.u64 %0, t; }" : "=r"(a) : "l"(p));
    return a;
}

#define CP16(dst, src) \
    asm volatile("cp.async.cg.shared.global [%0], [%1], 16;" :: "r"(dst), "l"(src))
#define CP_COMMIT() asm volatile("cp.async.commit_group;" ::: "memory")
#define CP_WAIT0()  asm volatile("cp.async.wait_group 0;" ::: "memory")

#define LDSM4(r, addr) \
    asm volatile("ldmatrix.sync.aligned.m8n8.x4.shared.b16 {%0,%1,%2,%3}, [%4];" \
                 : "=r"((r)[0]), "=r"((r)[1]), "=r"((r)[2]), "=r"((r)[3]) : "r"(addr))

#define MMA16816(c, a, b0, b1) \
    asm volatile("mma.sync.aligned.m16n8k16.row.col.f32.f16.f16.f32 " \
                 "{%0,%1,%2,%3}, {%4,%5,%6,%7}, {%8,%9}, {%0,%1,%2,%3};" \
                 : "+f"((c)[0]), "+f"((c)[1]), "+f"((c)[2]), "+f"((c)[3]) \
                 : "r"((a)[0]), "r"((a)[1]), "r"((a)[2]), "r"((a)[3]), \
                   "r"(b0), "r"(b1))

__device__ __forceinline__ uint32_t swz(uint32_t off) { return off ^ ((off >> 3) & 0x70); }

// ---------------- tile geometry (R7-proven) ----------------
#define BM 128
#define BN 128
#define BKT 64
#define OFF_A 0
#define OFF_B 16384
#define STAGE_TOTAL 32768
#define SMEM_DYN (2 * STAGE_TOTAL)

// ---------------- fp32 -> fp16 weight convert ----------------
__global__ __launch_bounds__(256) void cvt_w_kernel(const float4* __restrict__ w,
                                                    uint4* __restrict__ dst, int nw8) {
    int i = blockIdx.x * blockDim.x + threadIdx.x;
    if (i >= nw8) return;
    const float4* src = w + 2 * (size_t)i;
    float4 a = src[0], b = src[1];
    __half2 h0 = __floats2half2_rn(a.x, a.y), h1 = __floats2half2_rn(a.z, a.w);
    __half2 h2 = __floats2half2_rn(b.x, b.y), h3 = __floats2half2_rn(b.z, b.w);
    uint4 o;
    o.x = *(uint32_t*)&h0; o.y = *(uint32_t*)&h1;
    o.z = *(uint32_t*)&h2; o.w = *(uint32_t*)&h3;
    dst[i] = o;
}

// ---------------- router: 4 warps/token, 2 tokens/block + fused x cvt + psum ------
__global__ __launch_bounds__(256) void router_kernel(const float4* __restrict__ x4,
                                                     const float4* __restrict__ rw4) {
    const int lane = threadIdx.x & 31;
    const int wid = threadIdx.x >> 5;          // 0..7
    const int tkn = wid >> 2;                  // 0..1 token within block
    const int q = wid & 3;                     // 0..3 quarter of D
    const int n = blockIdx.x * 2 + tkn;

    __shared__ float pl[8][N_EXP];             // per-warp partial logits
    __shared__ float sp2[2][N_EXP];            // per-token probs (for psum)

    const float4* xr = x4 + (size_t)n * (D_MODEL / 4) + q * 64;
    uint2* xo = (uint2*)(g_x_f16 + (size_t)n * D_MODEL) + q * 64;
    const float4* rwq = rw4 + q * 64;

    float part[N_EXP];
#pragma unroll
    for (int e = 0; e < N_EXP; e++) part[e] = 0.f;
#pragma unroll
    for (int i = 0; i < 2; i++) {
        float4 v = xr[lane + 32 * i];
        __half2 p0 = __floats2half2_rn(v.x, v.y);
        __half2 p1 = __floats2half2_rn(v.z, v.w);
        uint2 pk;
        pk.x = *(uint32_t*)&p0; pk.y = *(uint32_t*)&p1;
        xo[lane + 32 * i] = pk;
#pragma unroll
        for (int e = 0; e < N_EXP; e++) {
            float4 w = rwq[e * (D_MODEL / 4) + lane + 32 * i];
            part[e] += v.x * w.x + v.y * w.y + v.z * w.z + v.w * w.w;
        }
    }
#pragma unroll
    for (int o = 16; o > 0; o >>= 1) {
#pragma unroll
        for (int e = 0; e < N_EXP; e++)
            part[e] += __shfl_xor_sync(0xFFFFFFFF, part[e], o);
    }
    if (lane == 0) {
#pragma unroll
        for (int e = 0; e < N_EXP; e++) pl[wid][e] = part[e];
    }
    __syncthreads();

    // one thread per token finalizes
    if (threadIdx.x < 2) {
        const int t = threadIdx.x;
        const int nt = blockIdx.x * 2 + t;
        float logit[N_EXP];
#pragma unroll
        for (int e = 0; e < N_EXP; e++)
            logit[e] = (pl[4 * t][e] + pl[4 * t + 1][e]) + (pl[4 * t + 2][e] + pl[4 * t + 3][e]);
        float m = logit[0];
#pragma unroll
        for (int e = 1; e < N_EXP; e++) m = fmaxf(m, logit[e]);
        float p[N_EXP], s = 0.f;
#pragma unroll
        for (int e = 0; e < N_EXP; e++) { p[e] = expf(logit[e] - m); s += p[e]; }
        float inv = 1.f / s;
#pragma unroll
        for (int e = 0; e < N_EXP; e++) { p[e] *= inv; sp2[t][e] = p[e]; }
        int i1 = 0;
#pragma unroll
        for (int e = 1; e < N_EXP; e++) if (logit[e] > logit[i1]) i1 = e;
        int i2 = (i1 == 0) ? 1 : 0;
#pragma unroll
        for (int e = 0; e < N_EXP; e++) if (e != i1 && logit[e] > logit[i2]) i2 = e;
        float denom = p[i1] + p[i2];
        int pos1 = atomicAdd(&g_cnt[i1], 1);
        g_tok[i1 * CAP + pos1] = nt; g_slot[i1 * CAP + pos1] = 2 * nt; g_wt[i1 * CAP + pos1] = p[i1] / denom;
        int pos2 = atomicAdd(&g_cnt[i2], 1);
        g_tok[i2 * CAP + pos2] = nt; g_slot[i2 * CAP + pos2] = 2 * nt + 1; g_wt[i2 * CAP + pos2] = p[i2] / denom;
    }
    __syncthreads();
    if (threadIdx.x < N_EXP) {
        float s = sp2[0][threadIdx.x] + sp2[1][threadIdx.x];
        atomicAdd(&g_psum[threadIdx.x], s);
    }
}

// ---------------- stage loader / compute (R7-proven) ----------------
__device__ __forceinline__ void load_stage(uint32_t st, int lr, int lc0,
                                           const __half* a, const __half* b, int k0) {
#pragma unroll
    for (int j = 0; j < 4; j++) {
        uint32_t off = (uint32_t)lr * 128 + (lc0 + j) * 16;
        uint32_t so = swz(off);
        CP16(st + OFF_A + so, (const void*)(a + k0 + (lc0 + j) * 8));
        CP16(st + OFF_B + so, (const void*)(b + k0 + (lc0 + j) * 8));
    }
    CP_COMMIT();
}

__device__ __forceinline__ void compute_stage(uint32_t sb, float acc[4][4][4],
                                              int wm, int wn, int lane) {
    const int arow = lane & 15, ahalf = lane >> 4;
    const int nrow = ((lane >> 4) & 1) * 8 + (lane & 7);
    const int bhalf = (lane >> 3) & 1;
#pragma unroll
    for (int kk = 0; kk < 4; kk++) {
        uint32_t ah[4][4], bf[2][4];
#pragma unroll
        for (int mi = 0; mi < 4; mi++) {
            uint32_t off = (uint32_t)(wm * 64 + mi * 16 + arow) * 128 + kk * 32 + ahalf * 16;
            LDSM4(ah[mi], sb + OFF_A + swz(off));
        }
#pragma unroll
        for (int p = 0; p < 2; p++) {
            uint32_t off = (uint32_t)(wn * 32 + p * 16 + nrow) * 128 + kk * 32 + bhalf * 16;
            LDSM4(bf[p], sb + OFF_B + swz(off));
        }
#pragma unroll
        for (int mi = 0; mi < 4; mi++) {
#pragma unroll
            for (int p = 0; p < 2; p++) {
                MMA16816(acc[mi][2 * p],     ah[mi], bf[p][0], bf[p][1]);
                MMA16816(acc[mi][2 * p + 1], ah[mi], bf[p][2], bf[p][3]);
            }
        }
    }
}

// ============ grouped GEMM1: h[slot] = silu(x[tok] @ w1[e]^T + b1[e]) ============
__global__ __launch_bounds__(256, 2) void gemm1_mma(const float* __restrict__ b1) {
    const int e = blockIdx.z;
    const int cnt = g_cnt[e];
    const int row0 = blockIdx.y * BM;
    if (row0 >= cnt) return;
    const int col0 = blockIdx.x * BN;

    extern __shared__ char sm[];
    __shared__ int toks[BM];
    __shared__ int slots[BM];

    const int tid = threadIdx.x;
    if (tid < BM) {
        int r = row0 + tid;
        toks[tid]  = (r < cnt) ? g_tok[e * CAP + r]  : 0;
        slots[tid] = (r < cnt) ? g_slot[e * CAP + r] : -1;
    }
    __syncthreads();

    const uint32_t smb = smem_u32(sm);
    const int lr = tid >> 1;
    const int lc0 = (tid & 1) * 4;

    const __half* aP = g_x_f16 + (size_t)toks[lr] * D_MODEL;
    const __half* bP = g_w1_f16 + ((size_t)e * FFN_H + col0 + lr) * D_MODEL;

    float acc[4][4][4];
#pragma unroll
    for (int mi = 0; mi < 4; mi++)
#pragma unroll
        for (int ni = 0; ni < 4; ni++)
#pragma unroll
            for (int q = 0; q < 4; q++) acc[mi][ni][q] = 0.f;

    const int lane = tid & 31;
    const int wid = tid >> 5;
    const int wm = wid >> 2, wn = wid & 3;
    const int NT = D_MODEL / BKT;   // 16

    load_stage(smb, lr, lc0, aP, bP, 0);

#pragma unroll 1
    for (int it = 0; it < NT; it++) {
        CP_WAIT0();
        __syncthreads();
        if (it + 1 < NT)
            load_stage(smb + ((it + 1) & 1) * STAGE_TOTAL, lr, lc0, aP, bP, (it + 1) * BKT);
        compute_stage(smb + (it & 1) * STAGE_TOTAL, acc, wm, wn, lane);
        __syncthreads();
    }

    // epilogue: bias + silu + fp16 store
    const int gr = lane >> 2, gc2 = (lane & 3) * 2;
    const float* b1e = b1 + (size_t)e * FFN_H;
#pragma unroll
    for (int mi = 0; mi < 4; mi++) {
#pragma unroll
        for (int ni = 0; ni < 4; ni++) {
            int col = col0 + wn * 32 + ni * 8 + gc2;
            float bv0 = b1e[col], bv1 = b1e[col + 1];
#pragma unroll
            for (int half = 0; half < 2; half++) {
                int r = wm * 64 + mi * 16 + gr + half * 8;
                int slot = slots[r];
                if (slot >= 0) {
                    float v0 = acc[mi][ni][half * 2 + 0] + bv0;
                    float v1 = acc[mi][ni][half * 2 + 1] + bv1;
                    float s0 = v0 / (1.f + expf(-v0));
                    float s1 = v1 / (1.f + expf(-v1));
                    *(__half2*)(g_h_f16 + (size_t)slot * FFN_H + col) = __floats2half2_rn(s0, s1);
                }
            }
        }
    }
}

// ============ grouped GEMM2: y[slot] = wt * (h[slot] @ w2[e]^T + b2[e]) ============
__global__ __launch_bounds__(256, 2) void gemm2_mma(const float* __restrict__ b2) {
    const int e = blockIdx.z;
    const int cnt = g_cnt[e];
    const int row0 = blockIdx.y * BM;
    if (row0 >= cnt) return;
    const int col0 = blockIdx.x * BN;

    extern __shared__ char sm[];
    __shared__ float wts[BM];
    __shared__ int   slots[BM];

    const int tid = threadIdx.x;
    if (tid < BM) {
        int r = row0 + tid;
        slots[tid] = (r < cnt) ? g_slot[e * CAP + r] : -1;
        wts[tid]   = (r < cnt) ? g_wt[e * CAP + r]   : 0.f;
    }
    __syncthreads();

    const uint32_t smb = smem_u32(sm);
    const int lr = tid >> 1;
    const int lc0 = (tid & 1) * 4;

    const int aslot = (slots[lr] < 0) ? 0 : slots[lr];
    const __half* aP = g_h_f16 + (size_t)aslot * FFN_H;
    const __half* bP = g_w2_f16 + ((size_t)e * D_MODEL + col0 + lr) * FFN_H;

    float acc[4][4][4];
#pragma unroll
    for (int mi = 0; mi < 4; mi++)
#pragma unroll
        for (int ni = 0; ni < 4; ni++)
#pragma unroll
            for (int q = 0; q < 4; q++) acc[mi][ni][q] = 0.f;

    const int lane = tid & 31;
    const int wid = tid >> 5;
    const int wm = wid >> 2, wn = wid & 3;
    const int NT = FFN_H / BKT;   // 32

    load_stage(smb, lr, lc0, aP, bP, 0);

#pragma unroll 1
    for (int it = 0; it < NT; it++) {
        CP_WAIT0();
        __syncthreads();
        if (it + 1 < NT)
            load_stage(smb + ((it + 1) & 1) * STAGE_TOTAL, lr, lc0, aP, bP, (it + 1) * BKT);
        compute_stage(smb + (it & 1) * STAGE_TOTAL, acc, wm, wn, lane);
        __syncthreads();
    }

    // epilogue: weighted + biased store to per-slot scratch (no atomics)
    const int gr = lane >> 2, gc2 = (lane & 3) * 2;
    const float* b2e = b2 + (size_t)e * D_MODEL;
#pragma unroll
    for (int mi = 0; mi < 4; mi++) {
#pragma unroll
        for (int ni = 0; ni < 4; ni++) {
            int col = col0 + wn * 32 + ni * 8 + gc2;
            float bv0 = b2e[col], bv1 = b2e[col + 1];
#pragma unroll
            for (int half = 0; half < 2; half++) {
                int r = wm * 64 + mi * 16 + gr + half * 8;
                int slot = slots[r];
                if (slot >= 0) {
                    float wt = wts[r];
                    float2 v;
                    v.x = (acc[mi][ni][half * 2 + 0] + bv0) * wt;
                    v.y = (acc[mi][ni][half * 2 + 1] + bv1) * wt;
                    *(float2*)(g_y + (size_t)slot * D_MODEL + col) = v;
                }
            }
        }
    }
}

// ---- combine: out[n] = y[2n] + y[2n+1]; aux loss; reset counters for next replay --
__global__ __launch_bounds__(256) void combine_kernel(float4* __restrict__ out4,
                                                      float* __restrict__ out,
                                                      int out_size) {
    int i = blockIdx.x * blockDim.x + threadIdx.x;
    const int D4 = D_MODEL / 4;
    if (i < N_TOK * D4) {
        int n = i / D4, rem = i - n * D4;
        const float4* ya = (const float4*)g_y + (size_t)(2 * n) * D4 + rem;
        const float4* yb = (const float4*)g_y + (size_t)(2 * n + 1) * D4 + rem;
        float4 a = *ya, b = *yb;
        float4 r;
        r.x = a.x + b.x; r.y = a.y + b.y; r.z = a.z + b.z; r.w = a.w + b.w;
        out4[i] = r;
    }
    if (blockIdx.x == 0 && threadIdx.x == 0) {
        float a = 0.f;
#pragma unroll
        for (int e = 0; e < N_EXP; e++) {
            float f = (float)g_cnt[e] / (float)(N_TOK * 2);
            float P = g_psum[e] / (float)N_TOK;
            a += f * P;
        }
        if (out_size > N_TOK * D_MODEL) out[N_TOK * D_MODEL] = a * (float)N_EXP;
        // reset routing state so the next graph replay starts from zeros
#pragma unroll
        for (int e = 0; e < N_EXP; e++) { g_cnt[e] = 0; g_psum[e] = 0.f; }
    }
}

// ---------------- launch ----------------
extern "C" void kernel_launch(void* const* d_in, const int* in_sizes, int n_in,
                              void* d_out, int out_size) {
    const float* x  = (const float*)d_in[0];
    const float* rw = (const float*)d_in[1];
    const float* w1 = (const float*)d_in[2];
    const float* b1 = (const float*)d_in[3];
    const float* w2 = (const float*)d_in[4];
    const float* b2 = (const float*)d_in[5];
    float* out = (float*)d_out;

    // one-time resource setup (first call = correctness run, pre-capture)
    static cudaStream_t s2 = nullptr;
    static cudaEvent_t evFork = nullptr, ev1 = nullptr, ev2 = nullptr;
    if (s2 == nullptr) {
        cudaStreamCreateWithFlags(&s2, cudaStreamNonBlocking);
        cudaEventCreateWithFlags(&evFork, cudaEventDisableTiming);
        cudaEventCreateWithFlags(&ev1, cudaEventDisableTiming);
        cudaEventCreateWithFlags(&ev2, cudaEventDisableTiming);
        cudaFuncSetAttribute(gemm1_mma, cudaFuncAttributeMaxDynamicSharedMemorySize, SMEM_DYN);
        cudaFuncSetAttribute(gemm2_mma, cudaFuncAttributeMaxDynamicSharedMemorySize, SMEM_DYN);
    }

    __half *w1h, *w2h;
    cudaGetSymbolAddress((void**)&w1h, g_w1_f16);
    cudaGetSymbolAddress((void**)&w2h, g_w2_f16);

    // fork: side stream does the weight conversions
    cudaEventRecord(evFork, 0);
    cudaStreamWaitEvent(s2, evFork, 0);
    const int nw8 = N_EXP * FFN_H * D_MODEL / 8;
    cvt_w_kernel<<<(nw8 + 255) / 256, 256, 0, s2>>>((const float4*)w1, (uint4*)w1h, nw8);
    cudaEventRecord(ev1, s2);
    cvt_w_kernel<<<(nw8 + 255) / 256, 256, 0, s2>>>((const float4*)w2, (uint4*)w2h, nw8);
    cudaEventRecord(ev2, s2);

    // main stream: routing (counters start at zero: static init on first call,
    // combine_kernel's tail reset on every subsequent replay)
    router_kernel<<<N_TOK / 2, 256>>>((const float4*)x, (const float4*)rw);

    cudaStreamWaitEvent(0, ev1, 0);            // w1 ready
    dim3 g1(FFN_H / BN, N_TOK / BM, N_EXP);
    gemm1_mma<<<g1, 256, SMEM_DYN>>>(b1);

    cudaStreamWaitEvent(0, ev2, 0);            // w2 ready
    dim3 g2(D_MODEL / BN, N_TOK / BM, N_EXP);
    gemm2_mma<<<g2, 256, SMEM_DYN>>>(b2);

    const int nc = N_TOK * (D_MODEL / 4);
    combine_kernel<<<(nc + 255) / 256, 256>>>((float4*)out, out, out_size);
}

// round 16
// speedup vs baseline: 1.0453x; 1.0243x over previous
#include <cuda_runtime.h>
#include <cuda_fp16.h>
#include <math.h>
#include <stdint.h>

#define D_MODEL 1024
#define N_EXP   8
#define N_TOK   4096
#define FFN_H   2048
#define CAP     N_TOK

// ---------------- device scratch (zero-initialized at module load) ----------------
__device__ int   g_cnt[N_EXP];
__device__ float g_psum[N_EXP];
__device__ int   g_tok[N_EXP * CAP];
__device__ int   g_slot[N_EXP * CAP];
__device__ float g_wt[N_EXP * CAP];

__device__ __align__(16) __half g_x_f16[(size_t)N_TOK * D_MODEL];
__device__ __align__(16) __half g_w1_f16[(size_t)N_EXP * FFN_H * D_MODEL];
__device__ __align__(16) __half g_w2_f16[(size_t)N_EXP * D_MODEL * FFN_H];
__device__ __align__(16) __half g_h_f16[(size_t)2 * N_TOK * FFN_H];
__device__ __align__(16) float  g_y[(size_t)2 * N_TOK * D_MODEL];

// ---------------- portable PTX helpers ----------------
__device__ __forceinline__ uint32_t smem_u32(const void* p) {
    uint32_t a;
    asm("{ .reg .u64 t; cvta.to.shared.u64 t, %1; cvt.u32.u64 %0, t; }" : "=r"(a) : "l"(p));
    return a;
}

#define CP16(dst, src) \
    asm volatile("cp.async.cg.shared.global [%0], [%1], 16;" :: "r"(dst), "l"(src))
#define CP_COMMIT() asm volatile("cp.async.commit_group;" ::: "memory")
#define CP_WAIT0()  asm volatile("cp.async.wait_group 0;" ::: "memory")

#define LDSM4(r, addr) \
    asm volatile("ldmatrix.sync.aligned.m8n8.x4.shared.b16 {%0,%1,%2,%3}, [%4];" \
                 : "=r"((r)[0]), "=r"((r)[1]), "=r"((r)[2]), "=r"((r)[3]) : "r"(addr))

#define MMA16816(c, a, b0, b1) \
    asm volatile("mma.sync.aligned.m16n8k16.row.col.f32.f16.f16.f32 " \
                 "{%0,%1,%2,%3}, {%4,%5,%6,%7}, {%8,%9}, {%0,%1,%2,%3};" \
                 : "+f"((c)[0]), "+f"((c)[1]), "+f"((c)[2]), "+f"((c)[3]) \
                 : "r"((a)[0]), "r"((a)[1]), "r"((a)[2]), "r"((a)[3]), \
                   "r"(b0), "r"(b1))

__device__ __forceinline__ uint32_t swz(uint32_t off) { return off ^ ((off >> 3) & 0x70); }

// fast silu: ~2^-21 relative error, well within the 4e-4 budget
__device__ __forceinline__ float fast_silu(float v) {
    return __fdividef(v, 1.f + __expf(-v));
}

// ---------------- tile geometry (R7-proven) ----------------
#define BM 128
#define BN 128
#define BKT 64
#define OFF_A 0
#define OFF_B 16384
#define STAGE_TOTAL 32768
#define SMEM_DYN (2 * STAGE_TOTAL)

// ---------------- fp32 -> fp16 weight convert ----------------
__global__ __launch_bounds__(256) void cvt_w_kernel(const float4* __restrict__ w,
                                                    uint4* __restrict__ dst, int nw8) {
    int i = blockIdx.x * blockDim.x + threadIdx.x;
    if (i >= nw8) return;
    const float4* src = w + 2 * (size_t)i;
    float4 a = src[0], b = src[1];
    __half2 h0 = __floats2half2_rn(a.x, a.y), h1 = __floats2half2_rn(a.z, a.w);
    __half2 h2 = __floats2half2_rn(b.x, b.y), h3 = __floats2half2_rn(b.z, b.w);
    uint4 o;
    o.x = *(uint32_t*)&h0; o.y = *(uint32_t*)&h1;
    o.z = *(uint32_t*)&h2; o.w = *(uint32_t*)&h3;
    dst[i] = o;
}

// ---------------- router: 4 warps/token, 2 tokens/block + fused x cvt + psum ------
__global__ __launch_bounds__(256) void router_kernel(const float4* __restrict__ x4,
                                                     const float4* __restrict__ rw4) {
    const int lane = threadIdx.x & 31;
    const int wid = threadIdx.x >> 5;          // 0..7
    const int tkn = wid >> 2;                  // 0..1 token within block
    const int q = wid & 3;                     // 0..3 quarter of D
    const int n = blockIdx.x * 2 + tkn;

    __shared__ float pl[8][N_EXP];             // per-warp partial logits
    __shared__ float sp2[2][N_EXP];            // per-token probs (for psum)

    const float4* xr = x4 + (size_t)n * (D_MODEL / 4) + q * 64;
    uint2* xo = (uint2*)(g_x_f16 + (size_t)n * D_MODEL) + q * 64;
    const float4* rwq = rw4 + q * 64;

    float part[N_EXP];
#pragma unroll
    for (int e = 0; e < N_EXP; e++) part[e] = 0.f;
#pragma unroll
    for (int i = 0; i < 2; i++) {
        float4 v = xr[lane + 32 * i];
        __half2 p0 = __floats2half2_rn(v.x, v.y);
        __half2 p1 = __floats2half2_rn(v.z, v.w);
        uint2 pk;
        pk.x = *(uint32_t*)&p0; pk.y = *(uint32_t*)&p1;
        xo[lane + 32 * i] = pk;
#pragma unroll
        for (int e = 0; e < N_EXP; e++) {
            float4 w = rwq[e * (D_MODEL / 4) + lane + 32 * i];
            part[e] += v.x * w.x + v.y * w.y + v.z * w.z + v.w * w.w;
        }
    }
#pragma unroll
    for (int o = 16; o > 0; o >>= 1) {
#pragma unroll
        for (int e = 0; e < N_EXP; e++)
            part[e] += __shfl_xor_sync(0xFFFFFFFF, part[e], o);
    }
    if (lane == 0) {
#pragma unroll
        for (int e = 0; e < N_EXP; e++) pl[wid][e] = part[e];
    }
    __syncthreads();

    // one thread per token finalizes
    if (threadIdx.x < 2) {
        const int t = threadIdx.x;
        const int nt = blockIdx.x * 2 + t;
        float logit[N_EXP];
#pragma unroll
        for (int e = 0; e < N_EXP; e++)
            logit[e] = (pl[4 * t][e] + pl[4 * t + 1][e]) + (pl[4 * t + 2][e] + pl[4 * t + 3][e]);
        float m = logit[0];
#pragma unroll
        for (int e = 1; e < N_EXP; e++) m = fmaxf(m, logit[e]);
        float p[N_EXP], s = 0.f;
#pragma unroll
        for (int e = 0; e < N_EXP; e++) { p[e] = expf(logit[e] - m); s += p[e]; }
        float inv = 1.f / s;
#pragma unroll
        for (int e = 0; e < N_EXP; e++) { p[e] *= inv; sp2[t][e] = p[e]; }
        int i1 = 0;
#pragma unroll
        for (int e = 1; e < N_EXP; e++) if (logit[e] > logit[i1]) i1 = e;
        int i2 = (i1 == 0) ? 1 : 0;
#pragma unroll
        for (int e = 0; e < N_EXP; e++) if (e != i1 && logit[e] > logit[i2]) i2 = e;
        float denom = p[i1] + p[i2];
        int pos1 = atomicAdd(&g_cnt[i1], 1);
        g_tok[i1 * CAP + pos1] = nt; g_slot[i1 * CAP + pos1] = 2 * nt; g_wt[i1 * CAP + pos1] = p[i1] / denom;
        int pos2 = atomicAdd(&g_cnt[i2], 1);
        g_tok[i2 * CAP + pos2] = nt; g_slot[i2 * CAP + pos2] = 2 * nt + 1; g_wt[i2 * CAP + pos2] = p[i2] / denom;
    }
    __syncthreads();
    if (threadIdx.x < N_EXP) {
        float s = sp2[0][threadIdx.x] + sp2[1][threadIdx.x];
        atomicAdd(&g_psum[threadIdx.x], s);
    }
}

// ---------------- stage loader / compute (R7-proven) ----------------
__device__ __forceinline__ void load_stage(uint32_t st, int lr, int lc0,
                                           const __half* a, const __half* b, int k0) {
#pragma unroll
    for (int j = 0; j < 4; j++) {
        uint32_t off = (uint32_t)lr * 128 + (lc0 + j) * 16;
        uint32_t so = swz(off);
        CP16(st + OFF_A + so, (const void*)(a + k0 + (lc0 + j) * 8));
        CP16(st + OFF_B + so, (const void*)(b + k0 + (lc0 + j) * 8));
    }
    CP_COMMIT();
}

__device__ __forceinline__ void compute_stage(uint32_t sb, float acc[4][4][4],
                                              int wm, int wn, int lane) {
    const int arow = lane & 15, ahalf = lane >> 4;
    const int nrow = ((lane >> 4) & 1) * 8 + (lane & 7);
    const int bhalf = (lane >> 3) & 1;
#pragma unroll
    for (int kk = 0; kk < 4; kk++) {
        uint32_t ah[4][4], bf[2][4];
#pragma unroll
        for (int mi = 0; mi < 4; mi++) {
            uint32_t off = (uint32_t)(wm * 64 + mi * 16 + arow) * 128 + kk * 32 + ahalf * 16;
            LDSM4(ah[mi], sb + OFF_A + swz(off));
        }
#pragma unroll
        for (int p = 0; p < 2; p++) {
            uint32_t off = (uint32_t)(wn * 32 + p * 16 + nrow) * 128 + kk * 32 + bhalf * 16;
            LDSM4(bf[p], sb + OFF_B + swz(off));
        }
#pragma unroll
        for (int mi = 0; mi < 4; mi++) {
#pragma unroll
            for (int p = 0; p < 2; p++) {
                MMA16816(acc[mi][2 * p],     ah[mi], bf[p][0], bf[p][1]);
                MMA16816(acc[mi][2 * p + 1], ah[mi], bf[p][2], bf[p][3]);
            }
        }
    }
}

// ============ grouped GEMM1: h[slot] = silu(x[tok] @ w1[e]^T + b1[e]) ============
__global__ __launch_bounds__(256, 2) void gemm1_mma(const float* __restrict__ b1) {
    const int e = blockIdx.z;
    const int cnt = g_cnt[e];
    const int row0 = blockIdx.y * BM;
    if (row0 >= cnt) return;
    const int col0 = blockIdx.x * BN;

    extern __shared__ char sm[];
    __shared__ int toks[BM];
    __shared__ int slots[BM];

    const int tid = threadIdx.x;
    if (tid < BM) {
        int r = row0 + tid;
        toks[tid]  = (r < cnt) ? g_tok[e * CAP + r]  : 0;
        slots[tid] = (r < cnt) ? g_slot[e * CAP + r] : -1;
    }
    __syncthreads();

    const uint32_t smb = smem_u32(sm);
    const int lr = tid >> 1;
    const int lc0 = (tid & 1) * 4;

    const __half* aP = g_x_f16 + (size_t)toks[lr] * D_MODEL;
    const __half* bP = g_w1_f16 + ((size_t)e * FFN_H + col0 + lr) * D_MODEL;

    float acc[4][4][4];
#pragma unroll
    for (int mi = 0; mi < 4; mi++)
#pragma unroll
        for (int ni = 0; ni < 4; ni++)
#pragma unroll
            for (int q = 0; q < 4; q++) acc[mi][ni][q] = 0.f;

    const int lane = tid & 31;
    const int wid = tid >> 5;
    const int wm = wid >> 2, wn = wid & 3;
    const int NT = D_MODEL / BKT;   // 16

    load_stage(smb, lr, lc0, aP, bP, 0);

#pragma unroll 1
    for (int it = 0; it < NT; it++) {
        CP_WAIT0();
        __syncthreads();
        if (it + 1 < NT)
            load_stage(smb + ((it + 1) & 1) * STAGE_TOTAL, lr, lc0, aP, bP, (it + 1) * BKT);
        compute_stage(smb + (it & 1) * STAGE_TOTAL, acc, wm, wn, lane);
        __syncthreads();
    }

    // epilogue: bias + fast silu + fp16 store
    const int gr = lane >> 2, gc2 = (lane & 3) * 2;
    const float* b1e = b1 + (size_t)e * FFN_H;
#pragma unroll
    for (int mi = 0; mi < 4; mi++) {
#pragma unroll
        for (int ni = 0; ni < 4; ni++) {
            int col = col0 + wn * 32 + ni * 8 + gc2;
            float bv0 = b1e[col], bv1 = b1e[col + 1];
#pragma unroll
            for (int half = 0; half < 2; half++) {
                int r = wm * 64 + mi * 16 + gr + half * 8;
                int slot = slots[r];
                if (slot >= 0) {
                    float v0 = acc[mi][ni][half * 2 + 0] + bv0;
                    float v1 = acc[mi][ni][half * 2 + 1] + bv1;
                    float s0 = fast_silu(v0);
                    float s1 = fast_silu(v1);
                    *(__half2*)(g_h_f16 + (size_t)slot * FFN_H + col) = __floats2half2_rn(s0, s1);
                }
            }
        }
    }
}

// ============ grouped GEMM2: y[slot] = wt * (h[slot] @ w2[e]^T + b2[e]) ============
__global__ __launch_bounds__(256, 2) void gemm2_mma(const float* __restrict__ b2) {
    const int e = blockIdx.z;
    const int cnt = g_cnt[e];
    const int row0 = blockIdx.y * BM;
    if (row0 >= cnt) return;
    const int col0 = blockIdx.x * BN;

    extern __shared__ char sm[];
    __shared__ float wts[BM];
    __shared__ int   slots[BM];

    const int tid = threadIdx.x;
    if (tid < BM) {
        int r = row0 + tid;
        slots[tid] = (r < cnt) ? g_slot[e * CAP + r] : -1;
        wts[tid]   = (r < cnt) ? g_wt[e * CAP + r]   : 0.f;
    }
    __syncthreads();

    const uint32_t smb = smem_u32(sm);
    const int lr = tid >> 1;
    const int lc0 = (tid & 1) * 4;

    const int aslot = (slots[lr] < 0) ? 0 : slots[lr];
    const __half* aP = g_h_f16 + (size_t)aslot * FFN_H;
    const __half* bP = g_w2_f16 + ((size_t)e * D_MODEL + col0 + lr) * FFN_H;

    float acc[4][4][4];
#pragma unroll
    for (int mi = 0; mi < 4; mi++)
#pragma unroll
        for (int ni = 0; ni < 4; ni++)
#pragma unroll
            for (int q = 0; q < 4; q++) acc[mi][ni][q] = 0.f;

    const int lane = tid & 31;
    const int wid = tid >> 5;
    const int wm = wid >> 2, wn = wid & 3;
    const int NT = FFN_H / BKT;   // 32

    load_stage(smb, lr, lc0, aP, bP, 0);

#pragma unroll 1
    for (int it = 0; it < NT; it++) {
        CP_WAIT0();
        __syncthreads();
        if (it + 1 < NT)
            load_stage(smb + ((it + 1) & 1) * STAGE_TOTAL, lr, lc0, aP, bP, (it + 1) * BKT);
        compute_stage(smb + (it & 1) * STAGE_TOTAL, acc, wm, wn, lane);
        __syncthreads();
    }

    // epilogue: weighted + biased store to per-slot scratch (no atomics)
    const int gr = lane >> 2, gc2 = (lane & 3) * 2;
    const float* b2e = b2 + (size_t)e * D_MODEL;
#pragma unroll
    for (int mi = 0; mi < 4; mi++) {
#pragma unroll
        for (int ni = 0; ni < 4; ni++) {
            int col = col0 + wn * 32 + ni * 8 + gc2;
            float bv0 = b2e[col], bv1 = b2e[col + 1];
#pragma unroll
            for (int half = 0; half < 2; half++) {
                int r = wm * 64 + mi * 16 + gr + half * 8;
                int slot = slots[r];
                if (slot >= 0) {
                    float wt = wts[r];
                    float2 v;
                    v.x = (acc[mi][ni][half * 2 + 0] + bv0) * wt;
                    v.y = (acc[mi][ni][half * 2 + 1] + bv1) * wt;
                    *(float2*)(g_y + (size_t)slot * D_MODEL + col) = v;
                }
            }
        }
    }
}

// ---- combine: out[n] = y[2n] + y[2n+1]; aux loss; reset counters for next replay --
__global__ __launch_bounds__(256) void combine_kernel(float4* __restrict__ out4,
                                                      float* __restrict__ out,
                                                      int out_size) {
    int i = blockIdx.x * blockDim.x + threadIdx.x;
    const int D4 = D_MODEL / 4;
    if (i < N_TOK * D4) {
        int n = i / D4, rem = i - n * D4;
        const float4* ya = (const float4*)g_y + (size_t)(2 * n) * D4 + rem;
        const float4* yb = (const float4*)g_y + (size_t)(2 * n + 1) * D4 + rem;
        float4 a = *ya, b = *yb;
        float4 r;
        r.x = a.x + b.x; r.y = a.y + b.y; r.z = a.z + b.z; r.w = a.w + b.w;
        out4[i] = r;
    }
    if (blockIdx.x == 0 && threadIdx.x == 0) {
        float a = 0.f;
#pragma unroll
        for (int e = 0; e < N_EXP; e++) {
            float f = (float)g_cnt[e] / (float)(N_TOK * 2);
            float P = g_psum[e] / (float)N_TOK;
            a += f * P;
        }
        if (out_size > N_TOK * D_MODEL) out[N_TOK * D_MODEL] = a * (float)N_EXP;
        // reset routing state so the next graph replay starts from zeros
#pragma unroll
        for (int e = 0; e < N_EXP; e++) { g_cnt[e] = 0; g_psum[e] = 0.f; }
    }
}

// ---------------- launch ----------------
extern "C" void kernel_launch(void* const* d_in, const int* in_sizes, int n_in,
                              void* d_out, int out_size) {
    const float* x  = (const float*)d_in[0];
    const float* rw = (const float*)d_in[1];
    const float* w1 = (const float*)d_in[2];
    const float* b1 = (const float*)d_in[3];
    const float* w2 = (const float*)d_in[4];
    const float* b2 = (const float*)d_in[5];
    float* out = (float*)d_out;

    // one-time resource setup (first call = correctness run, pre-capture)
    static cudaStream_t s2 = nullptr;
    static cudaEvent_t evFork = nullptr, ev1 = nullptr, ev2 = nullptr;
    if (s2 == nullptr) {
        cudaStreamCreateWithFlags(&s2, cudaStreamNonBlocking);
        cudaEventCreateWithFlags(&evFork, cudaEventDisableTiming);
        cudaEventCreateWithFlags(&ev1, cudaEventDisableTiming);
        cudaEventCreateWithFlags(&ev2, cudaEventDisableTiming);
        cudaFuncSetAttribute(gemm1_mma, cudaFuncAttributeMaxDynamicSharedMemorySize, SMEM_DYN);
        cudaFuncSetAttribute(gemm2_mma, cudaFuncAttributeMaxDynamicSharedMemorySize, SMEM_DYN);
    }

    __half *w1h, *w2h;
    cudaGetSymbolAddress((void**)&w1h, g_w1_f16);
    cudaGetSymbolAddress((void**)&w2h, g_w2_f16);

    // fork: side stream does the weight conversions
    cudaEventRecord(evFork, 0);
    cudaStreamWaitEvent(s2, evFork, 0);
    const int nw8 = N_EXP * FFN_H * D_MODEL / 8;
    cvt_w_kernel<<<(nw8 + 255) / 256, 256, 0, s2>>>((const float4*)w1, (uint4*)w1h, nw8);
    cudaEventRecord(ev1, s2);
    cvt_w_kernel<<<(nw8 + 255) / 256, 256, 0, s2>>>((const float4*)w2, (uint4*)w2h, nw8);
    cudaEventRecord(ev2, s2);

    // main stream: routing (counters start at zero: static init on first call,
    // combine_kernel's tail reset on every subsequent replay)
    router_kernel<<<N_TOK / 2, 256>>>((const float4*)x, (const float4*)rw);

    cudaStreamWaitEvent(0, ev1, 0);            // w1 ready
    dim3 g1(FFN_H / BN, N_TOK / BM, N_EXP);
    gemm1_mma<<<g1, 256, SMEM_DYN>>>(b1);

    cudaStreamWaitEvent(0, ev2, 0);            // w2 ready
    dim3 g2(D_MODEL / BN, N_TOK / BM, N_EXP);
    gemm2_mma<<<g2, 256, SMEM_DYN>>>(b2);

    const int nc = N_TOK * (D_MODEL / 4);
    combine_kernel<<<(nc + 255) / 256, 256>>>((float4*)out, out, out_size);
}